// round 5
// baseline (speedup 1.0000x reference)
#include <cuda_runtime.h>
#include <math.h>

#define NC 10
#define NG 8
#define TPB 256
#define WARPS (TPB / 32)
#define QCAP 256           // ring capacity per warp (power of 2)
#define BPC 60             // blocks per class
#define GRID (NC * BPC)

// Scratch (allocation-free rule: __device__ globals; zero-init at module load,
// the in-kernel finalize re-zeroes them so every graph replay starts clean).
__device__ float g_S[NC * NG];
__device__ float g_V[NC * NG];
__device__ float g_count[NC];
__device__ unsigned g_ticket;

// ---------------------------------------------------------------------------
// Single fused kernel: warp-compacted class scan + gather + last-block finalize.
// Each block owns ONE class. Warps scan labels (int4, coalesced) with a
// WARP-UNIFORM loop bound, ballot-compact matched row indices into a shared
// ring, and process full 32-lane batches: unconditional 32B row gathers +
// full-utilization logf/FMA, accumulating S_i and V_i = sum a_i*(R - log a_i).
// The last block to finish reduces the 80 (S,V) pairs to the scalar answer.
__global__ __launch_bounds__(TPB) void k_all(const float* __restrict__ act,
                                             const int* __restrict__ labels,
                                             int N, float* __restrict__ out) {
    const int c    = blockIdx.x / BPC;
    const int b    = blockIdx.x % BPC;
    const int w    = threadIdx.x >> 5;
    const int lane = threadIdx.x & 31;
    const int want = c + 1;
    const size_t clsBase = (size_t)c * (size_t)N;

    __shared__ int qbuf[WARPS][QCAP];
    __shared__ float sh[2 * NG + 1];
    __shared__ bool amLast;
    __shared__ float pc[NC];

    if (threadIdx.x < 2 * NG + 1) sh[threadIdx.x] = 0.0f;
    __syncthreads();

    float s[NG] = {0,0,0,0,0,0,0,0};
    float v[NG] = {0,0,0,0,0,0,0,0};

    unsigned head = 0, tail = 0;   // warp-uniform ring cursors

    const int nq = N >> 2;
    const int4* lab4 = (const int4*)labels;
    const int gw     = b * WARPS + w;          // global warp id within class
    const int stride = BPC * WARPS * 32;

    const unsigned ltmask = (1u << lane) - 1u;

    // Process one full batch of 32 queued rows (all lanes active).
    #define BATCH32()                                                           \
        {                                                                       \
            __syncwarp();                                                       \
            int idx = qbuf[w][(head + lane) & (QCAP - 1)];                      \
            head += 32;                                                         \
            const float4* r = (const float4*)(act + (clsBase + (size_t)idx) * NG); \
            float4 aq = r[0], bq = r[1];                                        \
            float a[NG] = {aq.x, aq.y, aq.z, aq.w, bq.x, bq.y, bq.z, bq.w};     \
            float la[NG]; float R = 0.0f;                                       \
            _Pragma("unroll")                                                   \
            for (int g = 0; g < NG; ++g) { la[g] = __logf(a[g]); R += la[g]; }  \
            _Pragma("unroll")                                                   \
            for (int g = 0; g < NG; ++g) {                                      \
                s[g] += a[g];                                                   \
                v[g] = fmaf(a[g], R - la[g], v[g]);                             \
            }                                                                   \
        }

    #define SLOT(LV, OFF)                                                      \
        {                                                                       \
            unsigned m = __ballot_sync(0xFFFFFFFFu, (LV) == want);              \
            if ((LV) == want)                                                   \
                qbuf[w][(tail + __popc(m & ltmask)) & (QCAP - 1)] = n + (OFF);  \
            tail += __popc(m);                                                  \
        }

    // Warp-uniform outer loop: 'base' is identical across the warp.
    for (int base = gw * 32; base < nq; base += stride) {
        int q = base + lane;
        int4 lb;
        if (q < nq) lb = lab4[q];
        else        { lb.x = 0; lb.y = 0; lb.z = 0; lb.w = 0; }
        int n = q << 2;
        SLOT(lb.x, 0) SLOT(lb.y, 1) SLOT(lb.z, 2) SLOT(lb.w, 3)
        while (tail - head >= 32) BATCH32()
    }

    // Scalar tail of labels (N % 4): warp 0 of block 0 per class, uniform loop.
    if (b == 0 && w == 0) {
        int tstart = nq << 2;
        for (int nb = tstart; nb < N; nb += 32) {
            int n = nb + lane;
            int lv = (n < N) ? labels[n] : 0;
            unsigned m = __ballot_sync(0xFFFFFFFFu, lv == want);
            if (lv == want)
                qbuf[w][(tail + __popc(m & ltmask)) & (QCAP - 1)] = n;
            tail += __popc(m);
            while (tail - head >= 32) BATCH32()
        }
    }

    // Drain remainder (<32) with predication (full warp executes).
    {
        unsigned rem = tail - head;
        __syncwarp();
        int idx = (lane < (int)rem) ? qbuf[w][(head + lane) & (QCAP - 1)] : 0;
        if (lane < (int)rem) {
            const float4* r = (const float4*)(act + (clsBase + (size_t)idx) * NG);
            float4 aq = r[0], bq = r[1];
            float a[NG] = {aq.x, aq.y, aq.z, aq.w, bq.x, bq.y, bq.z, bq.w};
            float la[NG]; float R = 0.0f;
            #pragma unroll
            for (int g = 0; g < NG; ++g) { la[g] = __logf(a[g]); R += la[g]; }
            #pragma unroll
            for (int g = 0; g < NG; ++g) {
                s[g] += a[g];
                v[g] = fmaf(a[g], R - la[g], v[g]);
            }
        }
    }
    #undef SLOT
    #undef BATCH32

    float cnt = (float)tail;   // warp-uniform: rows this warp enqueued

    // warp tree-reduce 16 values (full warp — all lanes alive here)
    #pragma unroll
    for (int o = 16; o > 0; o >>= 1) {
        #pragma unroll
        for (int g = 0; g < NG; ++g) {
            s[g] += __shfl_down_sync(0xFFFFFFFFu, s[g], o);
            v[g] += __shfl_down_sync(0xFFFFFFFFu, v[g], o);
        }
    }

    if (lane == 0) {
        #pragma unroll
        for (int g = 0; g < NG; ++g) {
            atomicAdd(&sh[g], s[g]);
            atomicAdd(&sh[NG + g], v[g]);
        }
        atomicAdd(&sh[2 * NG], cnt);
    }
    __syncthreads();
    if (threadIdx.x < NG) {
        atomicAdd(&g_S[c * NG + threadIdx.x], sh[threadIdx.x]);
        atomicAdd(&g_V[c * NG + threadIdx.x], sh[NG + threadIdx.x]);
    }
    if (threadIdx.x == 2 * NG) atomicAdd(&g_count[c], sh[2 * NG]);

    // ---- last-block finalize ----
    __threadfence();
    if (threadIdx.x == 0) {
        unsigned t = atomicAdd(&g_ticket, 1u);
        amLast = (t == (unsigned)(GRID - 1));
    }
    __syncthreads();
    if (!amLast) return;

    int t = threadIdx.x;
    if (t < NC) pc[t] = 0.0f;
    __syncthreads();
    if (t < NC * NG) {
        int cc = t / NG;
        float S = __ldcg(&g_S[t]);                 // bypass L1 (atomics live in L2)
        float V = __ldcg(&g_V[t]);
        float term = V / S - (float)(NG - 1) * logf(S);
        atomicAdd(&pc[cc], term);
    }
    __syncthreads();
    if (t == 0) {
        float num = 0.0f, vcnt = 0.0f;
        #pragma unroll
        for (int cc = 0; cc < NC; ++cc) {
            float cn = __ldcg(&g_count[cc]);
            if (cn >= 2.0f) { num += pc[cc]; vcnt += 1.0f; }
        }
        out[0] = num / (vcnt * (float)(NG * (NG - 1)));
        g_ticket = 0;                               // reset for next replay
    }
    // reset scratch so the next replay starts from zeros (deterministic)
    if (t < NC * NG) { g_S[t] = 0.0f; g_V[t] = 0.0f; }
    if (t < NC) g_count[t] = 0.0f;
}

// ---------------------------------------------------------------------------
extern "C" void kernel_launch(void* const* d_in, const int* in_sizes, int n_in,
                              void* d_out, int out_size) {
    const float* act  = (const float*)d_in[0];   // [C, N, G] float32
    const int* labels = (const int*)d_in[1];     // [N] int32
    const int N = in_sizes[1];

    k_all<<<GRID, TPB>>>(act, labels, N, (float*)d_out);
}